// round 16
// baseline (speedup 1.0000x reference)
#include <cuda_runtime.h>
#include <cstdint>

#define S_ 128
#define B_ 32
#define H_ 512
#define V_ 10000
#define L_ 2

#define NB_ 128            // persistent blocks (1/SM)
#define TPB_ 256

// ---------------- device scratch (no allocations allowed) ----------------
__device__ __align__(16) float g_ax0[S_ * B_ * 3 * H_];   // [s][b][3][512]
__device__ __align__(16) float g_tops[S_ * B_ * H_];      // [t*32+b][512]
__device__ __align__(16) float g_h0T[H_ * B_];            // transposed [o][b]
__device__ __align__(16) float g_h1T[H_ * B_];
__device__ __align__(16) float g_rh0T[H_ * B_];
__device__ __align__(16) float g_rh1T[H_ * B_];
// tree barrier state: 16 leaves (8 CTAs each) + root; all self-resetting
__device__ unsigned g_leaf[16 * 32];   // one counter per 128B line
__device__ unsigned g_rootcnt = 0;
__device__ unsigned g_rootgen = 0;

// ---------------- packed f32x2 helpers ------------------------------------
__device__ __forceinline__ unsigned long long pack2(float lo, float hi) {
    unsigned long long r;
    asm("mov.b64 %0, {%1, %2};" : "=l"(r) : "f"(lo), "f"(hi));
    return r;
}
__device__ __forceinline__ void unpack2(unsigned long long v, float& lo, float& hi) {
    asm("mov.b64 {%0, %1}, %2;" : "=f"(lo), "=f"(hi) : "l"(v));
}
__device__ __forceinline__ void ffma2(unsigned long long& d,
                                      unsigned long long a, unsigned long long b) {
    asm("fma.rn.f32x2 %0, %1, %2, %0;" : "+l"(d) : "l"(a), "l"(b));
}

// ---------------- tree grid barrier (self-resetting; replay-safe) ---------
// Arrival: 8-way leaf atomics (padded lines) -> 16-way root. Release: root
// gen bump; everyone polls root gen. All counters return to 0 every pass;
// gen is read fresh relative each time -> graph-replay safe.
__device__ __forceinline__ void gbar() {
    __syncthreads();
    if (threadIdx.x == 0) {
        __threadfence();  // release my CTA's prior global writes
        volatile unsigned* vgen = &g_rootgen;
        unsigned gen = *vgen;                 // must read BEFORE arrival
        unsigned* leaf = &g_leaf[(blockIdx.x >> 3) * 32];
        unsigned p = atomicAdd(leaf, 1u);
        if (p == 7u) {
            atomicExch(leaf, 0u);             // reset leaf BEFORE root arrive
            __threadfence();
            unsigned rp = atomicAdd(&g_rootcnt, 1u);
            if (rp == 15u) {
                atomicExch(&g_rootcnt, 0u);
                __threadfence();
                atomicAdd(&g_rootgen, 1u);    // release
            } else {
                while (*vgen == gen) { __nanosleep(10); }
            }
        } else {
            while (*vgen == gen) { __nanosleep(10); }
        }
        __threadfence();  // acquire: invalidate stale L1 lines (CCTL.IVALL)
    }
    __syncthreads();
}

__device__ __forceinline__ float sigmoidf_(float x) {
    return 1.0f / (1.0f + expf(-x));
}

// ---------------- Kernel 1: X0 = emb[tokens] @ Wx0[g] + bx0[g] ------------
// Ping-pong SMEM, 1 sync per k-tile, token loads hoisted out of k-loop.
__global__ __launch_bounds__(256, 2) void x0_gemm(const int* __restrict__ tok32,
                                                  const float* __restrict__ emb,
                                                  const float* __restrict__ Wx,
                                                  const float* __restrict__ bx) {
    const int g = blockIdx.z;
    const float* Bg = Wx + (size_t)g * H_ * H_;
    const float* bg = bx + g * H_;

    __shared__ float As[2][16][132];
    __shared__ float Bs[2][16][132];

    const int tid = threadIdx.x;
    const int bm = blockIdx.y * 128;
    const int bn = blockIdx.x * 128;

    int or_odd = 0;
#pragma unroll
    for (int i = 1; i < 64; i += 2) or_odd |= tok32[i];
    const int tstride = (or_odd == 0) ? 2 : 1;

    const int lr = tid >> 2;
    const int lc = (tid & 3) << 2;
    const int kr = tid >> 4;
    const int nc = (tid & 15) << 2;
    const int ty = tid >> 4, tx = tid & 15;

    const int tok0 = tok32[(size_t)(bm + lr) * tstride];
    const int tok1 = tok32[(size_t)(bm + lr + 64) * tstride];
    const float* arow0 = emb + (size_t)tok0 * H_ + lc;
    const float* arow1 = emb + (size_t)tok1 * H_ + lc;
    const float* brow  = Bg + (size_t)kr * H_ + bn + nc;

    unsigned long long acc2[8][4];
#pragma unroll
    for (int i = 0; i < 8; i++)
#pragma unroll
        for (int j = 0; j < 4; j++) acc2[i][j] = 0ull;

    // prologue: tile 0 -> buf 0
    float4 va0 = *(const float4*)(arow0);
    float4 va1 = *(const float4*)(arow1);
    float4 vb0 = *(const float4*)(brow);
    float4 vb1 = *(const float4*)(brow + 64);
    As[0][lc + 0][lr] = va0.x; As[0][lc + 1][lr] = va0.y;
    As[0][lc + 2][lr] = va0.z; As[0][lc + 3][lr] = va0.w;
    As[0][lc + 0][lr + 64] = va1.x; As[0][lc + 1][lr + 64] = va1.y;
    As[0][lc + 2][lr + 64] = va1.z; As[0][lc + 3][lr + 64] = va1.w;
    *(float4*)&Bs[0][kr][nc] = vb0;
    *(float4*)&Bs[0][kr][nc + 64] = vb1;
    __syncthreads();
    // prefetch tile 1
    va0 = *(const float4*)(arow0 + 16);
    va1 = *(const float4*)(arow1 + 16);
    vb0 = *(const float4*)(brow + 16 * H_);
    vb1 = *(const float4*)(brow + 16 * H_ + 64);

    int buf = 0;
    for (int t = 0; t < 32; t++) {
#pragma unroll
        for (int k = 0; k < 16; k++) {
            float4 a0 = *(const float4*)&As[buf][k][ty * 8];
            float4 a1 = *(const float4*)&As[buf][k][ty * 8 + 4];
            ulonglong2 b01 = *(const ulonglong2*)&Bs[buf][k][tx * 8];
            ulonglong2 b23 = *(const ulonglong2*)&Bs[buf][k][tx * 8 + 4];
            unsigned long long bp[4] = {b01.x, b01.y, b23.x, b23.y};
            float a[8] = {a0.x, a0.y, a0.z, a0.w, a1.x, a1.y, a1.z, a1.w};
#pragma unroll
            for (int i = 0; i < 8; i++) {
                unsigned long long ai = pack2(a[i], a[i]);
#pragma unroll
                for (int j = 0; j < 4; j++) ffma2(acc2[i][j], ai, bp[j]);
            }
        }
        if (t < 31) {   // store prefetched tile t+1 into other buffer
            int ob = buf ^ 1;
            As[ob][lc + 0][lr] = va0.x; As[ob][lc + 1][lr] = va0.y;
            As[ob][lc + 2][lr] = va0.z; As[ob][lc + 3][lr] = va0.w;
            As[ob][lc + 0][lr + 64] = va1.x; As[ob][lc + 1][lr + 64] = va1.y;
            As[ob][lc + 2][lr + 64] = va1.z; As[ob][lc + 3][lr + 64] = va1.w;
            *(float4*)&Bs[ob][kr][nc] = vb0;
            *(float4*)&Bs[ob][kr][nc + 64] = vb1;
            if (t < 30) {   // prefetch tile t+2
                int ko = 16 * (t + 2);
                va0 = *(const float4*)(arow0 + ko);
                va1 = *(const float4*)(arow1 + ko);
                vb0 = *(const float4*)(brow + (size_t)ko * H_);
                vb1 = *(const float4*)(brow + (size_t)ko * H_ + 64);
            }
        }
        __syncthreads();
        buf ^= 1;
    }
#pragma unroll
    for (int i = 0; i < 8; i++) {
        int m = bm + ty * 8 + i;
        size_t base = (size_t)m * (3 * H_) + (size_t)g * H_ + bn;
#pragma unroll
        for (int j = 0; j < 4; j++) {
            float c0, c1; unpack2(acc2[i][j], c0, c1);
            int n = tx * 8 + j * 2;
            g_ax0[base + n]     = c0 + bg[bn + n];
            g_ax0[base + n + 1] = c1 + bg[bn + n + 1];
        }
    }
}

// ---------------- Kernel 2: persistent pipelined recurrence ---------------
#define OFF_WSM 0
#define OFF_SH0 (9 * 512 * 4)
#define OFF_SH1 (OFF_SH0 + 512 * 32)
#define OFF_RED (OFF_SH1 + 512 * 32)
#define OFF_Z0  (OFF_RED + 16 * 32 * 4)
#define OFF_Z1  (OFF_Z0 + 128)
#define OFF_AXH (OFF_Z1 + 128)
#define OFF_BX1 (OFF_AXH + 128)
#define SMEM_FLT (OFF_BX1 + 16)
#define SMEM_BYTES (SMEM_FLT * 4)

__global__ __launch_bounds__(TPB_) void gru_rec(const float* __restrict__ Wx,
                                                const float* __restrict__ bx,
                                                const float* __restrict__ U,
                                                const float* __restrict__ h0in,
                                                float* hf_out) {
    extern __shared__ float smem[];
    float* wsm   = smem + OFF_WSM;
    float* sh0   = smem + OFF_SH0;
    float* sh1   = smem + OFF_SH1;
    float* s_red = smem + OFF_RED;     // [16][32][4]
    float* s_z0  = smem + OFF_Z0;      // [4][32]
    float* s_z1  = smem + OFF_Z1;
    float* s_axh = smem + OFF_AXH;
    float* s_bx1 = smem + OFF_BX1;     // [3][4]

    const int tid  = threadIdx.x;
    const int lane = tid & 31;
    const int wid  = tid >> 5;
    const int obase = blockIdx.x * 4;

    // one-time weight slice load: m 0..5 = U[l*3+g], 6..8 = Wx[1][g]
    for (int idx = tid; idx < 9 * 512; idx += TPB_) {
        int m = idx >> 9, i = idx & 511;
        const float* src = (m < 6)
            ? (U  + ((size_t)m * 512 + i) * 512 + obase)
            : (Wx + ((size_t)(3 + (m - 6)) * 512 + i) * 512 + obase);
        *(float4*)&wsm[(size_t)idx * 4] = *(const float4*)src;
    }
    if (tid < 12) s_bx1[tid] = bx[(size_t)(3 + (tid >> 2)) * 512 + obase + (tid & 3)];

    // init transposed hidden states
    {
        const int NT = NB_ * TPB_;
        for (int i = blockIdx.x * TPB_ + tid; i < 2 * B_ * H_; i += NT) {
            int l = i >> 14, rem = i & 16383, b = rem >> 9, o = rem & 511;
            (l ? g_h1T : g_h0T)[o * 32 + b] = h0in[i];
        }
    }
    gbar();

    for (int k = 0; k <= S_; k++) {
        // ================= Phase A =================
        {   // stage h0T, h1T (coalesced)
            const float4* s0 = (const float4*)g_h0T;
            const float4* s1 = (const float4*)g_h1T;
            float4* d0 = (float4*)sh0; float4* d1 = (float4*)sh1;
            for (int i = tid; i < 4096; i += TPB_) { d0[i] = s0[i]; d1[i] = s1[i]; }
        }
        __syncthreads();
        {   // 7 dots (d: 0=U00 1=U01 2=U10 3=U11 4..6=Wx1 g), flattened
            int cur = wid * 448;
            const int endall = cur + 448;
            int d = cur >> 9;
#pragma unroll
            for (int seg = 0; seg < 2; seg++) {
                unsigned long long a01 = 0ull, a23 = 0ull;
                if (cur < endall && d < 7) {
                    int stop = min(endall, (d + 1) << 9);
                    int m = (d < 2) ? d : ((d < 4) ? d + 1 : d + 2);
                    const float* hsv = (d == 2 || d == 3) ? sh1 : sh0;
                    const ulonglong2* wp = (const ulonglong2*)(wsm + (size_t)m * 2048);
#pragma unroll 8
                    for (int i = cur; i < stop; ++i) {
                        int il = i & 511;
                        ulonglong2 w = wp[il];
                        float hv = hsv[il * 32 + lane];
                        unsigned long long h2 = pack2(hv, hv);
                        ffma2(a01, w.x, h2);
                        ffma2(a23, w.y, h2);
                    }
                    cur = stop; d++;
                }
                float c0, c1, c2, c3;
                unpack2(a01, c0, c1); unpack2(a23, c2, c3);
                *(float4*)&s_red[((wid * 2 + seg) * 32 + lane) * 4] =
                    make_float4(c0, c1, c2, c3);
            }
        }
        __syncthreads();
        if (tid < 128) {   // combine: thread = (b=lane, oc=wid)
            const int b = lane, oc = wid;
            const int segd[16] = {0,1, 0,1, 1,2, 2,3, 3,4, 4,5, 5,6, 6,7};
            float dsum[7] = {0.f, 0.f, 0.f, 0.f, 0.f, 0.f, 0.f};
#pragma unroll
            for (int s = 0; s < 16; s++) {
                if (segd[s] < 7) dsum[segd[s]] += s_red[(s * 32 + b) * 4 + oc];
            }
            const int col = obase + oc;
            if (k < S_) {
                const float* axp = g_ax0 + ((size_t)(k * 32 + b) * 3) * 512 + col;
                float r0 = sigmoidf_(dsum[0] + axp[0]);
                float z0 = sigmoidf_(dsum[1] + axp[512]);
                s_z0[oc * 32 + b] = z0;
                g_rh0T[col * 32 + b] = r0 * sh0[col * 32 + b];
            }
            if (k >= 1) {
                float r1 = sigmoidf_(dsum[2] + dsum[4] + s_bx1[oc]);
                float z1 = sigmoidf_(dsum[3] + dsum[5] + s_bx1[4 + oc]);
                s_z1[oc * 32 + b] = z1;
                s_axh[oc * 32 + b] = dsum[6] + s_bx1[8 + oc];
                g_rh1T[col * 32 + b] = r1 * sh1[col * 32 + b];
            }
        }
        gbar();

        // ================= Phase B =================
        {   // stage rh0T, rh1T
            const float4* s0 = (const float4*)g_rh0T;
            const float4* s1 = (const float4*)g_rh1T;
            float4* d0 = (float4*)sh0; float4* d1 = (float4*)sh1;
            for (int i = tid; i < 4096; i += TPB_) { d0[i] = s0[i]; d1[i] = s1[i]; }
        }
        __syncthreads();
        {   // warps 0-3: U02·rh0 (K/4 each); warps 4-7: U12·rh1
            const int m = (wid < 4) ? 2 : 5;
            const float* hsv = (wid < 4) ? sh0 : sh1;
            const int i0 = (wid & 3) * 128;
            const ulonglong2* wp = (const ulonglong2*)(wsm + (size_t)m * 2048);
            unsigned long long a01 = 0ull, a23 = 0ull;
#pragma unroll 8
            for (int i = i0; i < i0 + 128; ++i) {
                ulonglong2 w = wp[i];
                float hv = hsv[i * 32 + lane];
                unsigned long long h2 = pack2(hv, hv);
                ffma2(a01, w.x, h2);
                ffma2(a23, w.y, h2);
            }
            float c0, c1, c2, c3;
            unpack2(a01, c0, c1); unpack2(a23, c2, c3);
            *(float4*)&s_red[(wid * 32 + lane) * 4] = make_float4(c0, c1, c2, c3);
        }
        __syncthreads();
        if (tid < 128) {
            const int b = lane, oc = wid;
            const int col = obase + oc;
            if (k < S_) {
                float dsum = s_red[(0 * 32 + b) * 4 + oc] + s_red[(1 * 32 + b) * 4 + oc]
                           + s_red[(2 * 32 + b) * 4 + oc] + s_red[(3 * 32 + b) * 4 + oc];
                float axh0 = g_ax0[((size_t)(k * 32 + b) * 3 + 2) * 512 + col];
                float hh = tanhf(axh0 + dsum);
                float z = s_z0[oc * 32 + b];
                float hold = g_h0T[col * 32 + b];
                g_h0T[col * 32 + b] = hold + z * (hh - hold);
            }
            if (k >= 1) {
                float dsum = s_red[(4 * 32 + b) * 4 + oc] + s_red[(5 * 32 + b) * 4 + oc]
                           + s_red[(6 * 32 + b) * 4 + oc] + s_red[(7 * 32 + b) * 4 + oc];
                float hh = tanhf(s_axh[oc * 32 + b] + dsum);
                float z = s_z1[oc * 32 + b];
                float hold = g_h1T[col * 32 + b];
                float hnew = hold + z * (hh - hold);
                g_h1T[col * 32 + b] = hnew;
                g_tops[((size_t)(k - 1) * 32 + b) * 512 + col] = hnew;
            }
        }
        gbar();
    }

    if (hf_out) {   // h_final [L][B][H] from transposed state
        const int NT = NB_ * TPB_;
        for (int i = blockIdx.x * TPB_ + tid; i < 2 * B_ * H_; i += NT) {
            int l = i >> 14, rem = i & 16383, b = rem >> 9, o = rem & 511;
            hf_out[i] = (l ? g_h1T : g_h0T)[o * 32 + b];
        }
    }
}

// ---------------- Kernel 3: logits = tops @ Wy^T + by ---------------------
// Ping-pong SMEM, 1 sync per k-tile.
__global__ __launch_bounds__(256, 2) void logits_gemm(const float* __restrict__ Wy,
                                                      const float* __restrict__ by,
                                                      float* __restrict__ out) {
    __shared__ float As[2][16][132];
    __shared__ float Bs[2][16][132];

    const int tid = threadIdx.x;
    const int bm = blockIdx.y * 128;
    const int bn = blockIdx.x * 128;
    const int lr = tid >> 2;
    const int lc = (tid & 3) << 2;
    const int ty = tid >> 4, tx = tid & 15;

    const float* arow0 = g_tops + (size_t)(bm + lr) * H_ + lc;
    const float* arow1 = g_tops + (size_t)(bm + lr + 64) * H_ + lc;
    const int n0 = bn + lr, n1 = bn + lr + 64;
    const float* brow0 = Wy + (size_t)n0 * H_ + lc;
    const float* brow1 = Wy + (size_t)n1 * H_ + lc;
    const bool v0 = (n0 < V_), v1 = (n1 < V_);

    unsigned long long acc2[8][4];
#pragma unroll
    for (int i = 0; i < 8; i++)
#pragma unroll
        for (int j = 0; j < 4; j++) acc2[i][j] = 0ull;

    const float4 fz = make_float4(0.f, 0.f, 0.f, 0.f);
    // prologue: tile 0 -> buf 0
    float4 va0 = *(const float4*)(arow0);
    float4 va1 = *(const float4*)(arow1);
    float4 vb0 = v0 ? *(const float4*)(brow0) : fz;
    float4 vb1 = v1 ? *(const float4*)(brow1) : fz;
    As[0][lc + 0][lr] = va0.x; As[0][lc + 1][lr] = va0.y;
    As[0][lc + 2][lr] = va0.z; As[0][lc + 3][lr] = va0.w;
    As[0][lc + 0][lr + 64] = va1.x; As[0][lc + 1][lr + 64] = va1.y;
    As[0][lc + 2][lr + 64] = va1.z; As[0][lc + 3][lr + 64] = va1.w;
    Bs[0][lc + 0][lr] = vb0.x; Bs[0][lc + 1][lr] = vb0.y;
    Bs[0][lc + 2][lr] = vb0.z; Bs[0][lc + 3][lr] = vb0.w;
    Bs[0][lc + 0][lr + 64] = vb1.x; Bs[0][lc + 1][lr + 64] = vb1.y;
    Bs[0][lc + 2][lr + 64] = vb1.z; Bs[0][lc + 3][lr + 64] = vb1.w;
    __syncthreads();
    va0 = *(const float4*)(arow0 + 16);
    va1 = *(const float4*)(arow1 + 16);
    vb0 = v0 ? *(const float4*)(brow0 + 16) : fz;
    vb1 = v1 ? *(const float4*)(brow1 + 16) : fz;

    int buf = 0;
    for (int t = 0; t < 32; t++) {
#pragma unroll
        for (int k = 0; k < 16; k++) {
            float4 a0 = *(const float4*)&As[buf][k][ty * 8];
            float4 a1 = *(const float4*)&As[buf][k][ty * 8 + 4];
            ulonglong2 b01 = *(const ulonglong2*)&Bs[buf][k][tx * 8];
            ulonglong2 b23 = *(const ulonglong2*)&Bs[buf][k][tx * 8 + 4];
            unsigned long long bp[4] = {b01.x, b01.y, b23.x, b23.y};
            float a[8] = {a0.x, a0.y, a0.z, a0.w, a1.x, a1.y, a1.z, a1.w};
#pragma unroll
            for (int i = 0; i < 8; i++) {
                unsigned long long ai = pack2(a[i], a[i]);
#pragma unroll
                for (int j = 0; j < 4; j++) ffma2(acc2[i][j], ai, bp[j]);
            }
        }
        if (t < 31) {
            int ob = buf ^ 1;
            As[ob][lc + 0][lr] = va0.x; As[ob][lc + 1][lr] = va0.y;
            As[ob][lc + 2][lr] = va0.z; As[ob][lc + 3][lr] = va0.w;
            As[ob][lc + 0][lr + 64] = va1.x; As[ob][lc + 1][lr + 64] = va1.y;
            As[ob][lc + 2][lr + 64] = va1.z; As[ob][lc + 3][lr + 64] = va1.w;
            Bs[ob][lc + 0][lr] = vb0.x; Bs[ob][lc + 1][lr] = vb0.y;
            Bs[ob][lc + 2][lr] = vb0.z; Bs[ob][lc + 3][lr] = vb0.w;
            Bs[ob][lc + 0][lr + 64] = vb1.x; Bs[ob][lc + 1][lr + 64] = vb1.y;
            Bs[ob][lc + 2][lr + 64] = vb1.z; Bs[ob][lc + 3][lr + 64] = vb1.w;
            if (t < 30) {
                int ko = 16 * (t + 2);
                va0 = *(const float4*)(arow0 + ko);
                va1 = *(const float4*)(arow1 + ko);
                vb0 = v0 ? *(const float4*)(brow0 + ko) : fz;
                vb1 = v1 ? *(const float4*)(brow1 + ko) : fz;
            }
        }
        __syncthreads();
        buf ^= 1;
    }
#pragma unroll
    for (int i = 0; i < 8; i++) {
        int m = bm + ty * 8 + i;
#pragma unroll
        for (int j = 0; j < 4; j++) {
            float c0, c1; unpack2(acc2[i][j], c0, c1);
            int n = bn + tx * 8 + j * 2;
            if (n < V_)     out[(size_t)m * V_ + n]     = c0 + by[n];
            if (n + 1 < V_) out[(size_t)m * V_ + n + 1] = c1 + by[n + 1];
        }
    }
}

// ---------------- launch --------------------------------------------------
extern "C" void kernel_launch(void* const* d_in, const int* in_sizes, int n_in,
                              void* d_out, int out_size) {
    const int*   tok32 = (const int*)d_in[0];
    const float* h0    = (const float*)d_in[1];
    const float* emb   = (const float*)d_in[2];
    const float* Wx    = (const float*)d_in[3];
    const float* bx    = (const float*)d_in[4];
    const float* U     = (const float*)d_in[5];
    const float* Wy    = (const float*)d_in[6];
    const float* by    = (const float*)d_in[7];
    float* out = (float*)d_out;

    // 1) layer-0 input projections for all timesteps
    dim3 gx(H_ / 128, (S_ * B_) / 128, 3);
    x0_gemm<<<gx, 256>>>(tok32, emb, Wx, bx);

    // 2) persistent pipelined recurrence
    static int smem_set = 0;
    if (!smem_set) {
        cudaFuncSetAttribute(gru_rec, cudaFuncAttributeMaxDynamicSharedMemorySize,
                             SMEM_BYTES);
        smem_set = 1;
    }
    float* hf = nullptr;
    long long need = (long long)S_ * B_ * V_ + (long long)L_ * B_ * H_;
    if ((long long)out_size >= need) hf = out + (size_t)S_ * B_ * V_;

    gru_rec<<<NB_, TPB_, SMEM_BYTES>>>(Wx, bx, U, h0, hf);

    // 3) logits projection
    dim3 gl((V_ + 127) / 128, (S_ * B_) / 128);
    logits_gemm<<<gl, 256>>>(Wy, by, out);
}